// round 5
// baseline (speedup 1.0000x reference)
#include <cuda_runtime.h>
#include <cuda_bf16.h>
#include <mma.h>
#include <cstdint>

using namespace nvcuda;

// ---------------- problem constants ----------------
#define BATCH      4
#define N1_PER     16384
#define N2_PER     4096
#define N1_TOT     (BATCH * N1_PER)    // 65536
#define N2_TOT     (BATCH * N2_PER)    // 16384
#define C_IN       512
#define C_OUT      256
#define BN_EPS     1e-5f

// ---------------- device scratch (static, allocation-free) ----------------
__device__ float g_h2[N2_TOT * C_OUT];                    // 16 MB
__device__ __nv_bfloat16 g_x1h[N1_TOT * C_OUT];
__device__ __nv_bfloat16 g_x1l[N1_TOT * C_OUT];
__device__ __nv_bfloat16 g_x2h[N2_TOT * C_IN];
__device__ __nv_bfloat16 g_x2l[N2_TOT * C_IN];
__device__ __nv_bfloat16 g_W1h[C_OUT * C_OUT];
__device__ __nv_bfloat16 g_W1l[C_OUT * C_OUT];
__device__ __nv_bfloat16 g_W2h[C_OUT * C_IN];
__device__ __nv_bfloat16 g_W2l[C_OUT * C_IN];
__device__ float g_c1[C_OUT];
__device__ float g_c2[C_OUT];

// ---------------- cp.async helpers ----------------
__device__ __forceinline__ void cp_async16(uint32_t smem, const void* gptr) {
    asm volatile("cp.async.cg.shared.global [%0], [%1], 16;" :: "r"(smem), "l"(gptr));
}
__device__ __forceinline__ void cp_commit() {
    asm volatile("cp.async.commit_group;");
}
__device__ __forceinline__ void cp_wait0() {
    asm volatile("cp.async.wait_group 0;");
}

// -------- BN fold + bf16 split of weights ---------------------------------
template <int WHICH>
__global__ void fold_convert_W(const float* __restrict__ W, const float* __restrict__ b,
                               const float* __restrict__ g, const float* __restrict__ be,
                               const float* __restrict__ m, const float* __restrict__ v)
{
    const int Kd = (WHICH == 0) ? C_OUT : C_IN;
    __nv_bfloat16* Wh = (WHICH == 0) ? g_W1h : g_W2h;
    __nv_bfloat16* Wl = (WHICH == 0) ? g_W1l : g_W2l;
    float* cf = (WHICH == 0) ? g_c1 : g_c2;
    int n = blockIdx.x;
    float s = g[n] / sqrtf(v[n] + BN_EPS);
    if (threadIdx.x == 0) cf[n] = (b[n] - m[n]) * s + be[n];
    for (int k = threadIdx.x; k < Kd; k += blockDim.x) {
        float w = W[n * Kd + k] * s;
        __nv_bfloat16 h = __float2bfloat16(w);
        Wh[n * Kd + k] = h;
        Wl[n * Kd + k] = __float2bfloat16(w - __bfloat162float(h));
    }
}

// -------- bf16 split of activations ---------------------------------------
__global__ void convert_x(const float* __restrict__ x,
                          __nv_bfloat16* __restrict__ xh,
                          __nv_bfloat16* __restrict__ xl, int n)
{
    int i = (blockIdx.x * blockDim.x + threadIdx.x) * 4;
    if (i >= n) return;
    float4 v = *(const float4*)(x + i);
    __nv_bfloat16 h0 = __float2bfloat16(v.x), h1 = __float2bfloat16(v.y);
    __nv_bfloat16 h2 = __float2bfloat16(v.z), h3 = __float2bfloat16(v.w);
    __nv_bfloat16 l0 = __float2bfloat16(v.x - __bfloat162float(h0));
    __nv_bfloat16 l1 = __float2bfloat16(v.y - __bfloat162float(h1));
    __nv_bfloat16 l2 = __float2bfloat16(v.z - __bfloat162float(h2));
    __nv_bfloat16 l3 = __float2bfloat16(v.w - __bfloat162float(h3));
    ushort4 ph = make_ushort4(__bfloat16_as_ushort(h0), __bfloat16_as_ushort(h1),
                              __bfloat16_as_ushort(h2), __bfloat16_as_ushort(h3));
    ushort4 pl = make_ushort4(__bfloat16_as_ushort(l0), __bfloat16_as_ushort(l1),
                              __bfloat16_as_ushort(l2), __bfloat16_as_ushort(l3));
    *(ushort4*)(xh + i) = ph;
    *(ushort4*)(xl + i) = pl;
}

// -------- tensor-core GEMM: C = relu( Ah*Bh + Ah*Bl + Al*Bh + bias ) ------
// One fused K-loop: per K-32 step load Ah, Al, Bh, Bl tiles (cp.async,
// double-buffered), issue all three MMA combos from one fragment set.
// Block tile 128x128, 8 warps (2 x 4), warp tile 64x32 (4x2 wmma frags).
#define LDS_AB 40
#define LDS_C  132
#define TILE_ELEMS (128 * LDS_AB)

template <int WHICH>
__global__ __launch_bounds__(256) void gemm_wmma(float* __restrict__ Cout)
{
    constexpr int K = (WHICH == 0) ? C_OUT : C_IN;
    constexpr int NSTEP = K / 32;

    const __nv_bfloat16* __restrict__ Ah = (WHICH == 0) ? g_x1h : g_x2h;
    const __nv_bfloat16* __restrict__ Al = (WHICH == 0) ? g_x1l : g_x2l;
    const __nv_bfloat16* __restrict__ Bh = (WHICH == 0) ? g_W1h : g_W2h;
    const __nv_bfloat16* __restrict__ Bl = (WHICH == 0) ? g_W1l : g_W2l;
    const float* __restrict__ cb = (WHICH == 0) ? g_c1 : g_c2;
    float* __restrict__ Cp = (WHICH == 0) ? Cout : g_h2;

    extern __shared__ __align__(16) char smem_raw[];
    __nv_bfloat16* tiles = (__nv_bfloat16*)smem_raw;  // [2][4][TILE_ELEMS]: Ah,Al,Bh,Bl
    float* Cs = (float*)smem_raw;                     // [128][132] (epilogue)

    const int tid = threadIdx.x;
    const int wid = tid >> 5;
    const int warp_m = wid >> 2;          // 0..1
    const int warp_n = wid & 3;           // 0..3
    const int bn = blockIdx.x * 128;
    const int bm = blockIdx.y * 128;

    wmma::fragment<wmma::accumulator, 16, 16, 16, float> acc[4][2];
#pragma unroll
    for (int i = 0; i < 4; i++)
#pragma unroll
        for (int j = 0; j < 2; j++) wmma::fill_fragment(acc[i][j], 0.0f);

    const uint32_t smem_base = (uint32_t)__cvta_generic_to_shared(tiles);

    // per k-step: 4 tiles x 128 rows x 32 cols = 2048 16B-chunks; 8 per thread
    auto load_tiles = [&](int s, int buf) {
        const int kk = s * 32;
        const uint32_t bufoff = (uint32_t)buf * 4 * TILE_ELEMS * 2;  // bytes
#pragma unroll
        for (int j = 0; j < 8; j++) {
            int idx = tid + j * 256;                 // 0..2047
            int t   = idx >> 9;                      // 0..3
            int w   = idx & 511;
            int r   = w >> 2;
            int c   = (w & 3) * 8;                   // element offset in 32
            const __nv_bfloat16* src;
            if (t == 0)      src = Ah + (size_t)(bm + r) * K + kk + c;
            else if (t == 1) src = Al + (size_t)(bm + r) * K + kk + c;
            else if (t == 2) src = Bh + (size_t)(bn + r) * K + kk + c;
            else             src = Bl + (size_t)(bn + r) * K + kk + c;
            uint32_t dst = smem_base + bufoff +
                           (uint32_t)(t * TILE_ELEMS + r * LDS_AB + c) * 2;
            cp_async16(dst, src);
        }
        cp_commit();
    };

    load_tiles(0, 0);

    for (int s = 0; s < NSTEP; s++) {
        const int buf = s & 1;
        cp_wait0();
        __syncthreads();
        if (s + 1 < NSTEP) load_tiles(s + 1, buf ^ 1);

        const __nv_bfloat16* tAh = tiles + (size_t)buf * 4 * TILE_ELEMS;
        const __nv_bfloat16* tAl = tAh + TILE_ELEMS;
        const __nv_bfloat16* tBh = tAl + TILE_ELEMS;
        const __nv_bfloat16* tBl = tBh + TILE_ELEMS;

#pragma unroll
        for (int kf = 0; kf < 2; kf++) {
            wmma::fragment<wmma::matrix_a, 16, 16, 16, __nv_bfloat16, wmma::row_major> afh[4];
            wmma::fragment<wmma::matrix_b, 16, 16, 16, __nv_bfloat16, wmma::col_major> bfh[2], bfl[2];
#pragma unroll
            for (int i = 0; i < 4; i++)
                wmma::load_matrix_sync(afh[i], tAh + (warp_m * 64 + i * 16) * LDS_AB + kf * 16, LDS_AB);
#pragma unroll
            for (int j = 0; j < 2; j++) {
                wmma::load_matrix_sync(bfh[j], tBh + (warp_n * 32 + j * 16) * LDS_AB + kf * 16, LDS_AB);
                wmma::load_matrix_sync(bfl[j], tBl + (warp_n * 32 + j * 16) * LDS_AB + kf * 16, LDS_AB);
            }
            // Ah*Bh + Ah*Bl
#pragma unroll
            for (int i = 0; i < 4; i++)
#pragma unroll
                for (int j = 0; j < 2; j++) {
                    wmma::mma_sync(acc[i][j], afh[i], bfh[j], acc[i][j]);
                    wmma::mma_sync(acc[i][j], afh[i], bfl[j], acc[i][j]);
                }
            // Al*Bh (reuse afh registers by overwriting with Al frags)
#pragma unroll
            for (int i = 0; i < 4; i++)
                wmma::load_matrix_sync(afh[i], tAl + (warp_m * 64 + i * 16) * LDS_AB + kf * 16, LDS_AB);
#pragma unroll
            for (int i = 0; i < 4; i++)
#pragma unroll
                for (int j = 0; j < 2; j++)
                    wmma::mma_sync(acc[i][j], afh[i], bfh[j], acc[i][j]);
        }
        __syncthreads();
    }

    // epilogue: dump accum to smem (fp32), then bias + relu + vectorized store
#pragma unroll
    for (int i = 0; i < 4; i++)
#pragma unroll
        for (int j = 0; j < 2; j++)
            wmma::store_matrix_sync(Cs + (warp_m * 64 + i * 16) * LDS_C + warp_n * 32 + j * 16,
                                    acc[i][j], LDS_C, wmma::mem_row_major);
    __syncthreads();

    const int r = tid >> 1;
    const int cbase = (tid & 1) * 64;
    const float* csrow = Cs + r * LDS_C + cbase;
    float* orow = Cp + (size_t)(bm + r) * 256 + bn + cbase;
#pragma unroll
    for (int t = 0; t < 16; t++) {
        float4 v = *(const float4*)(csrow + t * 4);
        float4 bv = *(const float4*)(cb + bn + cbase + t * 4);
        v.x = fmaxf(v.x + bv.x, 0.f);
        v.y = fmaxf(v.y + bv.y, 0.f);
        v.z = fmaxf(v.z + bv.z, 0.f);
        v.w = fmaxf(v.w + bv.w, 0.f);
        *(float4*)(orow + t * 4) = v;
    }
}

#define GEMM_SMEM (8 * TILE_ELEMS * 2 > 128 * LDS_C * 4 ? 8 * TILE_ELEMS * 2 : 128 * LDS_C * 4)

// ---------------- kNN(k=3) + inverse-distance interp + add into out -------
// Exact distances (reference-identical), 2 queries per thread to amortize
// each LDS.128 across two top-3 updates. grid: (N1_PER/512, BATCH).
#define TOP3_UPD(s, kk, A0, A1, A2, I0, I1, I2)            \
    if (s < A2) {                                          \
        if (s < A1) {                                      \
            A2 = A1; I2 = I1;                              \
            if (s < A0) { A1 = A0; I1 = I0; A0 = s; I0 = kk; } \
            else        { A1 = s;  I1 = kk; }              \
        } else { A2 = s; I2 = kk; }                        \
    }

__global__ __launch_bounds__(256) void knn_interp_kernel(
    const float* __restrict__ p1, const float* __restrict__ p2,
    float* __restrict__ out)
{
    extern __shared__ float4 pts[];   // [4096]

    const int scene = blockIdx.y;
    const int tid   = threadIdx.x;

    const float* p2s = p2 + (size_t)scene * N2_PER * 3;
    for (int i = tid; i < N2_PER; i += 256) {
        pts[i] = make_float4(p2s[3 * i + 0], p2s[3 * i + 1], p2s[3 * i + 2], 0.f);
    }
    __syncthreads();

    const int qA = scene * N1_PER + blockIdx.x * 512 + tid;
    const int qB = qA + 256;
    const float qAx = p1[3 * qA + 0], qAy = p1[3 * qA + 1], qAz = p1[3 * qA + 2];
    const float qBx = p1[3 * qB + 0], qBy = p1[3 * qB + 1], qBz = p1[3 * qB + 2];

    float a0 = 3.4e38f, a1 = 3.4e38f, a2 = 3.4e38f;
    float c0 = 3.4e38f, c1 = 3.4e38f, c2 = 3.4e38f;
    int   ia0 = 0, ia1 = 0, ia2 = 0;
    int   ib0 = 0, ib1 = 0, ib2 = 0;

#pragma unroll 4
    for (int k = 0; k < N2_PER; k++) {
        float4 p = pts[k];
        float dxA = qAx - p.x, dyA = qAy - p.y, dzA = qAz - p.z;
        float dA  = fmaf(dxA, dxA, fmaf(dyA, dyA, dzA * dzA));
        float dxB = qBx - p.x, dyB = qBy - p.y, dzB = qBz - p.z;
        float dB  = fmaf(dxB, dxB, fmaf(dyB, dyB, dzB * dzB));
        TOP3_UPD(dA, k, a0, a1, a2, ia0, ia1, ia2);
        TOP3_UPD(dB, k, c0, c1, c2, ib0, ib1, ib2);
    }

    float wA0 = 1.f / (sqrtf(fmaxf(a0, 1e-12f)) + 1e-8f);
    float wA1 = 1.f / (sqrtf(fmaxf(a1, 1e-12f)) + 1e-8f);
    float wA2 = 1.f / (sqrtf(fmaxf(a2, 1e-12f)) + 1e-8f);
    float ws = wA0 + wA1 + wA2;
    wA0 /= ws; wA1 /= ws; wA2 /= ws;

    float wB0 = 1.f / (sqrtf(fmaxf(c0, 1e-12f)) + 1e-8f);
    float wB1 = 1.f / (sqrtf(fmaxf(c1, 1e-12f)) + 1e-8f);
    float wB2 = 1.f / (sqrtf(fmaxf(c2, 1e-12f)) + 1e-8f);
    float ws2 = wB0 + wB1 + wB2;
    wB0 /= ws2; wB1 /= ws2; wB2 /= ws2;

    // warp-cooperative gather with coalesced float4 row streaming
    const unsigned full = 0xffffffffu;
    const int warp = tid >> 5, lane = tid & 31;
    const int h2base = scene * N2_PER;

#pragma unroll
    for (int half = 0; half < 2; half++) {
        float w0 = half ? wB0 : wA0, w1 = half ? wB1 : wA1, w2 = half ? wB2 : wA2;
        int   j0 = half ? ib0 : ia0, j1 = half ? ib1 : ia1, j2 = half ? ib2 : ia2;
        const int qbase = scene * N1_PER + blockIdx.x * 512 + half * 256 + warp * 32;

        for (int s = 0; s < 32; s++) {
            float ww0 = __shfl_sync(full, w0, s);
            float ww1 = __shfl_sync(full, w1, s);
            float ww2 = __shfl_sync(full, w2, s);
            int   t0  = __shfl_sync(full, j0, s);
            int   t1  = __shfl_sync(full, j1, s);
            int   t2  = __shfl_sync(full, j2, s);
            const float4* r0 = (const float4*)(g_h2 + (size_t)(h2base + t0) * 256);
            const float4* r1 = (const float4*)(g_h2 + (size_t)(h2base + t1) * 256);
            const float4* r2 = (const float4*)(g_h2 + (size_t)(h2base + t2) * 256);
            float4* o = (float4*)(out + (size_t)(qbase + s) * 256);
#pragma unroll
            for (int c = 0; c < 2; c++) {
                int ci = lane + c * 32;
                float4 x = r0[ci], y = r1[ci], z = r2[ci], ov = o[ci];
                ov.x += ww0 * x.x + ww1 * y.x + ww2 * z.x;
                ov.y += ww0 * x.y + ww1 * y.y + ww2 * z.y;
                ov.z += ww0 * x.z + ww1 * y.z + ww2 * z.z;
                ov.w += ww0 * x.w + ww1 * y.w + ww2 * z.w;
                o[ci] = ov;
            }
        }
    }
}

// ---------------- launch -----------------
extern "C" void kernel_launch(void* const* d_in, const int* in_sizes, int n_in,
                              void* d_out, int out_size)
{
    const float* p1  = (const float*)d_in[0];
    const float* x1  = (const float*)d_in[1];
    const float* p2  = (const float*)d_in[2];
    const float* x2  = (const float*)d_in[3];
    const float* W1  = (const float*)d_in[4];
    const float* b1  = (const float*)d_in[5];
    const float* g1  = (const float*)d_in[6];
    const float* be1 = (const float*)d_in[7];
    const float* m1  = (const float*)d_in[8];
    const float* v1  = (const float*)d_in[9];
    const float* W2  = (const float*)d_in[10];
    const float* b2  = (const float*)d_in[11];
    const float* g2  = (const float*)d_in[12];
    const float* be2 = (const float*)d_in[13];
    const float* m2  = (const float*)d_in[14];
    const float* v2  = (const float*)d_in[15];
    float* out = (float*)d_out;

    static bool attr_set = false;
    if (!attr_set) {
        cudaFuncSetAttribute(gemm_wmma<0>, cudaFuncAttributeMaxDynamicSharedMemorySize, GEMM_SMEM);
        cudaFuncSetAttribute(gemm_wmma<1>, cudaFuncAttributeMaxDynamicSharedMemorySize, GEMM_SMEM);
        cudaFuncSetAttribute(knn_interp_kernel, cudaFuncAttributeMaxDynamicSharedMemorySize,
                             N2_PER * (int)sizeof(float4));
        attr_set = true;
    }

    // fold BN into weights + bf16 split
    fold_convert_W<0><<<C_OUT, 128>>>(W1, b1, g1, be1, m1, v1);
    fold_convert_W<1><<<C_OUT, 128>>>(W2, b2, g2, be2, m2, v2);

    // bf16 split of activations
    {
        __nv_bfloat16 *x1h, *x1l, *x2h, *x2l;
        cudaGetSymbolAddress((void**)&x1h, g_x1h);
        cudaGetSymbolAddress((void**)&x1l, g_x1l);
        cudaGetSymbolAddress((void**)&x2h, g_x2h);
        cudaGetSymbolAddress((void**)&x2l, g_x2l);
        int n1 = N1_TOT * C_OUT, n2 = N2_TOT * C_IN;
        convert_x<<<n1 / 4 / 256, 256>>>(x1, x1h, x1l, n1);
        convert_x<<<n2 / 4 / 256, 256>>>(x2, x2h, x2l, n2);
    }

    // h1 = relu(bn(x1@W1^T)) -> out
    {
        dim3 grid1(2, N1_TOT / 128);
        gemm_wmma<0><<<grid1, 256, GEMM_SMEM>>>(out);
    }
    // h2 = relu(bn(x2@W2^T)) -> g_h2
    {
        dim3 grid2(2, N2_TOT / 128);
        gemm_wmma<1><<<grid2, 256, GEMM_SMEM>>>(out);
    }

    // kNN interpolation, accumulate into out
    dim3 gridk(N1_PER / 512, BATCH);
    knn_interp_kernel<<<gridk, 256, N2_PER * sizeof(float4)>>>(p1, p2, out);
}